// round 16
// baseline (speedup 1.0000x reference)
#include <cuda_runtime.h>
#include <math.h>

#define N_ANCH   8400
#define TOPK     10
#define ROI      3
#define NCHAN    256
#define FH       20
#define IOU_TH   0.45f
#define NT       1024
#define CAND_MAX 1536
#define NBANDS   10
#define R_CAP    4          // register slots per lane; fast-path capacity 128
#define MCAP     128        // suppression-matrix capacity
#define FULL     0xffffffffu
#define NV       (N_ANCH / 4)   // 2100 float4 chunks

// ---------------------------------------------------------------------------
// One kernel, 90 blocks; each block redundantly runs banded greedy NMS, then
// emits its own (keep k, roi-point p) x 256-channel output slice.
//
// NMS equivalence (R2-R15 notes): descending-score greedy; bands partition
// scores downward from 0.99; a lower band is materialized only when
// keeps < TOPK. Selection: max score, tie -> min original index (jnp.argmax),
// via unique keys / dense ranks -> identical keep set in every block
// regardless of atomicAdd slot order.
//
// R16: conf loads hoisted above barrier 1 (latency overlaps barrier skew);
// per-chunk fmax-tree early-out skips per-element tests when no candidate;
// box loads remain unconditional+batched after barrier 1 (R15 property).
// ---------------------------------------------------------------------------

__device__ __forceinline__ void scan_chunk5(int v, float4 cf,
                                            float4 xx, float4 yy,
                                            float4 ww, float4 hh,
                                            int* s_count,
                                            unsigned long long* c_key,
                                            float4* c_box)
{
    // early-out: no element in this chunk can pass
    if (fmaxf(fmaxf(cf.x, cf.y), fmaxf(cf.z, cf.w)) < 0.99f) return;

    float cfa[4] = {cf.x, cf.y, cf.z, cf.w};
    float xa [4] = {xx.x, xx.y, xx.z, xx.w};
    float ya [4] = {yy.x, yy.y, yy.z, yy.w};
    float wa [4] = {ww.x, ww.y, ww.z, ww.w};
    float ha [4] = {hh.x, hh.y, hh.z, hh.w};
    #pragma unroll
    for (int j = 0; j < 4; j++) {
        float c = cfa[j];
        if (c >= 0.99f) {
            int slot = atomicAdd(s_count, 1);
            if (slot < CAND_MAX) {
                int a = v * 4 + j;
                c_key[slot] = ((unsigned long long)__float_as_uint(c) << 32)
                            | (unsigned long long)(0x7fffffffu - (unsigned)a);
                float wh = wa[j] * 0.5f, hh2 = ha[j] * 0.5f;
                c_box[slot] = make_float4(xa[j] - wh, ya[j] - hh2,
                                          xa[j] + wh, ya[j] + hh2);
            }
        }
    }
}

__global__ __launch_bounds__(NT) void fused_kernel(const float* __restrict__ pred,
                                                   const float* __restrict__ feat,
                                                   float* __restrict__ out)
{
    __shared__ unsigned long long c_key[CAND_MAX];
    __shared__ float4  c_box[CAND_MAX];
    __shared__ unsigned s_T[MCAP * 4];        // T[j] word w: bits i in [32w,32w+32)
    __shared__ int     s_rank[MCAP];          // # candidates with larger key
    __shared__ int     s_count, s_old, s_keeps;
    __shared__ float4  s_kbox[TOPK];

    const int tid  = threadIdx.x;
    const int lane = tid & 31;

    const float*  __restrict__ px = pred;
    const float*  __restrict__ py = pred + N_ANCH;
    const float*  __restrict__ pw = pred + 2 * N_ANCH;
    const float*  __restrict__ ph = pred + 3 * N_ANCH;
    const float4* __restrict__ px4 = (const float4*)(pred);
    const float4* __restrict__ py4 = (const float4*)(pred + N_ANCH);
    const float4* __restrict__ pw4 = (const float4*)(pred + 2 * N_ANCH);
    const float4* __restrict__ ph4 = (const float4*)(pred + 3 * N_ANCH);
    const float4* __restrict__ pc4 = (const float4*)(pred + 4 * N_ANCH);

    // ---- conf loads issued BEFORE barrier 1: latency overlaps barrier skew
    const bool has2 = (tid + 2 * NT < NV);
    float4 cf0 = pc4[tid];                        // tid < 1024 <= 2100
    float4 cf1 = pc4[tid + NT];                   // tid+1024 <= 2047 < 2100
    float4 cf2 = has2 ? pc4[tid + 2 * NT] : make_float4(0.f, 0.f, 0.f, 0.f);

    if (tid == 0) { s_count = 0; s_keeps = 0; }
    if (tid < MCAP * 4) s_T[tid] = 0u;
    if (tid < MCAP) s_rank[tid] = 0;
    __syncthreads();                                          // barrier 1

    // ---- phase 1: unconditional batched box loads, then process ----
    {
        float4 xx0 = px4[tid],      xx1 = px4[tid + NT];
        float4 yy0 = py4[tid],      yy1 = py4[tid + NT];
        float4 ww0 = pw4[tid],      ww1 = pw4[tid + NT];
        float4 hh0 = ph4[tid],      hh1 = ph4[tid + NT];
        scan_chunk5(tid,      cf0, xx0, yy0, ww0, hh0, &s_count, c_key, c_box);
        scan_chunk5(tid + NT, cf1, xx1, yy1, ww1, hh1, &s_count, c_key, c_box);
        if (has2) {
            float4 xx2 = px4[tid + 2 * NT];
            float4 yy2 = py4[tid + 2 * NT];
            float4 ww2 = pw4[tid + 2 * NT];
            float4 hh2 = ph4[tid + 2 * NT];
            scan_chunk5(tid + 2 * NT, cf2, xx2, yy2, ww2, hh2, &s_count, c_key, c_box);
        }
    }
    __syncthreads();                                          // barrier 2

    const int count0 = min(s_count, CAND_MAX);
    const bool fast = (count0 <= MCAP);

    // ---- phase 2: suppression matrix + dense ranks, contiguous ranges ----
    if (fast) {
        const int n = count0;
        const int npairs = n * (n + 1) / 2;          // pairs with i <= j
        const int per = (npairs + NT - 1) / NT;
        int t    = tid * per;
        int tend = min(t + per, npairs);
        if (t < tend) {
            // one-time inversion t -> (i, j); row i starts at C(i)=i*n-i(i-1)/2
            const float fn2 = 2.0f * (float)n + 1.0f;
            int i = (int)((fn2 - sqrtf(fn2 * fn2 - 8.0f * (float)t)) * 0.5f);
            while (i * n - (i * (i - 1)) / 2 > t) i--;
            while ((i + 1) * n - ((i + 1) * i) / 2 <= t) i++;
            int j = i + (t - (i * n - (i * (i - 1)) / 2));

            for (; t < tend; t++) {
                if (i == j) {                         // diagonal = self (ar == i)
                    atomicOr(&s_T[j * 4 + (i >> 5)], 1u << (i & 31));
                } else {
                    // rank: increment the pair's smaller key (unique keys)
                    atomicAdd(&s_rank[c_key[i] < c_key[j] ? i : j], 1);

                    float4 bi = c_box[i], bj = c_box[j];
                    float lx = fmaxf(bi.x, bj.x), ly = fmaxf(bi.y, bj.y);
                    float rx = fminf(bi.z, bj.z), ry = fminf(bi.w, bj.w);
                    float inter = fmaxf(rx - lx, 0.f) * fmaxf(ry - ly, 0.f);
                    float a1 = fmaxf(bi.z - bi.x, 0.f) * fmaxf(bi.w - bi.y, 0.f);
                    float a2 = fmaxf(bj.z - bj.x, 0.f) * fmaxf(bj.w - bj.y, 0.f);
                    if (inter / fmaxf(a1 + a2 - inter, 1e-9f) > IOU_TH) {
                        atomicOr(&s_T[j * 4 + (i >> 5)], 1u << (i & 31));
                        atomicOr(&s_T[i * 4 + (j >> 5)], 1u << (j & 31));
                    }
                }
                if (++j == n) { ++i; j = i; }
            }
        }
    }
    __syncthreads();                                          // barrier 3

    // ---- warp 0: serial greedy selection (one redux per round) ----
    if (tid < 32) {
        int keeps = 0;

        if (fast) {
            unsigned val[R_CAP];                  // ((n-rank)<<7)|slot, 0 = dead
            unsigned cw[R_CAP][4];                // T column words, in registers
            #pragma unroll
            for (int r = 0; r < R_CAP; r++) {
                int j = r * 32 + lane;
                if (j < count0) {
                    val[r] = (((unsigned)(count0 - s_rank[j])) << 7) | (unsigned)j;
                    #pragma unroll
                    for (int w = 0; w < 4; w++) cw[r][w] = s_T[j * 4 + w];
                } else {
                    val[r] = 0u;
                    #pragma unroll
                    for (int w = 0; w < 4; w++) cw[r][w] = 0u;
                }
            }

            while (keeps < TOPK) {
                // local max over 4 unique values (pairwise tree)
                unsigned m01 = val[0] > val[1] ? val[0] : val[1];
                unsigned m23 = val[2] > val[3] ? val[2] : val[3];
                unsigned bv  = m01 > m23 ? m01 : m23;

                unsigned vm = __reduce_max_sync(FULL, bv);
                if (vm == 0u) break;                      // pool exhausted
                int wj = (int)(vm & 127u);

                if ((wj & 31) == lane) s_kbox[keeps] = c_box[wj];  // winner lane

                unsigned whi = (unsigned)wj >> 5, wlo = (unsigned)wj & 31u;
                #pragma unroll
                for (int r = 0; r < R_CAP; r++) {
                    unsigned word = (whi & 2u)
                        ? ((whi & 1u) ? cw[r][3] : cw[r][2])
                        : ((whi & 1u) ? cw[r][1] : cw[r][0]);
                    if ((word >> wlo) & 1u) val[r] = 0u;  // kill
                }
                keeps++;
            }
            if (keeps < TOPK) {       // write back kills for the cold ladder
                #pragma unroll
                for (int r = 0; r < R_CAP; r++) {
                    int j = r * 32 + lane;
                    if (j < count0 && val[r] == 0u) c_key[j] = 0ULL;
                }
            }
        } else {
            // oversized band-0 pool: smem loop (correct for any seed)
            while (keeps < TOPK) {
                unsigned long long bk = 0ULL; int bslot = 0;
                for (int j = lane; j < count0; j += 32) {
                    unsigned long long kk = c_key[j];
                    if (kk > bk) { bk = kk; bslot = j; }
                }
                #pragma unroll
                for (int o = 16; o; o >>= 1) {
                    unsigned long long ok_ = __shfl_xor_sync(FULL, bk, o);
                    int                os_ = __shfl_xor_sync(FULL, bslot, o);
                    if (ok_ > bk) { bk = ok_; bslot = os_; }
                }
                if (bk == 0ULL) break;
                float4 bbx = c_box[bslot];
                if (lane == 0) s_kbox[keeps] = bbx;
                float a1 = fmaxf(bbx.z - bbx.x, 0.f) * fmaxf(bbx.w - bbx.y, 0.f);
                for (int j = lane; j < count0; j += 32) {
                    if (c_key[j] == 0ULL) continue;
                    float4 b = c_box[j];
                    float lx = fmaxf(bbx.x, b.x), ly = fmaxf(bbx.y, b.y);
                    float rx = fminf(bbx.z, b.z), ry = fminf(bbx.w, b.w);
                    float inter = fmaxf(rx - lx, 0.f) * fmaxf(ry - ly, 0.f);
                    float a2 = fmaxf(b.z - b.x, 0.f) * fmaxf(b.w - b.y, 0.f);
                    if (inter / fmaxf(a1 + a2 - inter, 1e-9f) > IOU_TH) c_key[j] = 0ULL;
                }
                __syncwarp();
                keeps++;
            }
        }
        if (lane == 0) s_keeps = keeps;
    }
    __syncthreads();                                          // barrier 4

    // ---- cold path: descend bands until TOPK keeps or scores exhausted ----
    if (s_keeps < TOPK) {
        const float lo_tab[NBANDS] = {0.99f, 0.93f, 0.87f, 0.80f, 0.72f,
                                      0.64f, 0.55f, 0.45f, 0.35f, 0.25f};
        for (int band = 1; band < NBANDS; band++) {
            if (tid == 0) s_old = s_count;
            __syncthreads();
            const float lo = lo_tab[band], hi = lo_tab[band - 1];
            for (int v = tid; v < NV; v += NT) {
                float4 cf = pc4[v];
                float cfa[4] = {cf.x, cf.y, cf.z, cf.w};
                #pragma unroll
                for (int j = 0; j < 4; j++) {
                    float c = cfa[j];
                    if (c >= lo && c < hi) {
                        int slot = atomicAdd(&s_count, 1);
                        if (slot < CAND_MAX) {
                            int a = v * 4 + j;
                            c_key[slot] = ((unsigned long long)__float_as_uint(c) << 32)
                                        | (unsigned long long)(0x7fffffffu - (unsigned)a);
                            float x = px[a], y = py[a];
                            float wh = pw[a] * 0.5f, hh = ph[a] * 0.5f;
                            c_box[slot] = make_float4(x - wh, y - hh, x + wh, y + hh);
                        }
                    }
                }
            }
            __syncthreads();

            if (tid < 32) {
                int count = min(s_count, CAND_MAX);
                int keeps = s_keeps;
                int nold  = s_old;
                for (int ki = 0; ki < keeps; ki++) {
                    float4 kb = s_kbox[ki];
                    float a1 = fmaxf(kb.z - kb.x, 0.f) * fmaxf(kb.w - kb.y, 0.f);
                    for (int j = nold + lane; j < count; j += 32) {
                        float4 b = c_box[j];
                        float lx = fmaxf(kb.x, b.x), ly = fmaxf(kb.y, b.y);
                        float rx = fminf(kb.z, b.z), ry = fminf(kb.w, b.w);
                        float inter = fmaxf(rx - lx, 0.f) * fmaxf(ry - ly, 0.f);
                        float a2 = fmaxf(b.z - b.x, 0.f) * fmaxf(b.w - b.y, 0.f);
                        if (inter / fmaxf(a1 + a2 - inter, 1e-9f) > IOU_TH) c_key[j] = 0ULL;
                    }
                }
                __syncwarp();
                while (keeps < TOPK) {
                    unsigned long long bk = 0ULL; int bslot = 0;
                    for (int j = lane; j < count; j += 32) {
                        unsigned long long kk = c_key[j];
                        if (kk > bk) { bk = kk; bslot = j; }
                    }
                    #pragma unroll
                    for (int o = 16; o; o >>= 1) {
                        unsigned long long ok_ = __shfl_xor_sync(FULL, bk, o);
                        int                os_ = __shfl_xor_sync(FULL, bslot, o);
                        if (ok_ > bk) { bk = ok_; bslot = os_; }
                    }
                    if (bk == 0ULL) break;
                    float4 bbx = c_box[bslot];
                    if (lane == 0) s_kbox[keeps] = bbx;
                    float a1 = fmaxf(bbx.z - bbx.x, 0.f) * fmaxf(bbx.w - bbx.y, 0.f);
                    for (int j = lane; j < count; j += 32) {
                        if (c_key[j] == 0ULL) continue;
                        float4 b = c_box[j];
                        float lx = fmaxf(bbx.x, b.x), ly = fmaxf(bbx.y, b.y);
                        float rx = fminf(bbx.z, b.z), ry = fminf(bbx.w, b.w);
                        float inter = fmaxf(rx - lx, 0.f) * fmaxf(ry - ly, 0.f);
                        float a2 = fmaxf(b.z - b.x, 0.f) * fmaxf(b.w - b.y, 0.f);
                        if (inter / fmaxf(a1 + a2 - inter, 1e-9f) > IOU_TH) c_key[j] = 0ULL;
                    }
                    __syncwarp();
                    keeps++;
                }
                if (lane == 0) s_keeps = keeps;
            }
            __syncthreads();
            if (s_keeps >= TOPK) break;
        }
    }

    // ---- ROI-align: this block's (k, p) slice (first NCHAN threads) ----
    const int c = tid;
    if (c >= NCHAN) return;

    const int b = blockIdx.x;
    const int k = b / (ROI * ROI);
    const int p = b - k * (ROI * ROI);

    float* o = out + b * NCHAN + c;
    if (k >= s_keeps) { *o = 0.f; return; }

    const float scale = (float)FH / 640.0f;
    const float4 kb = s_kbox[k];
    const float sx1 = kb.x * scale, sy1 = kb.y * scale;
    const float sx2 = kb.z * scale, sy2 = kb.w * scale;
    const float bw = fmaxf(sx2 - sx1, 1e-6f) / (float)ROI;
    const float bh = fmaxf(sy2 - sy1, 1e-6f) / (float)ROI;

    const int gy = p / ROI;
    const int gx = p - gy * ROI;
    const float yg = sy1 + ((float)gy + 0.5f) * bh;
    const float xg = sx1 + ((float)gx + 0.5f) * bw;

    const float fy = floorf(yg), fx = floorf(xg);
    const float wy = yg - fy,    wx = xg - fx;

    int y0  = min(max((int)fy, 0), FH - 1);
    int x0  = min(max((int)fx, 0), FH - 1);
    int y1i = min(y0 + 1, FH - 1);
    int x1i = min(x0 + 1, FH - 1);

    const float* f = feat + c * (FH * FH);
    float v00 = f[y0  * FH + x0 ];
    float v01 = f[y0  * FH + x1i];
    float v10 = f[y1i * FH + x0 ];
    float v11 = f[y1i * FH + x1i];

    *o = v00 * (1.f - wy) * (1.f - wx)
       + v01 * (1.f - wy) * wx
       + v10 * wy * (1.f - wx)
       + v11 * wy * wx;
}

// ---------------------------------------------------------------------------
extern "C" void kernel_launch(void* const* d_in, const int* in_sizes, int n_in,
                              void* d_out, int out_size)
{
    const float* pred = (const float*)d_in[0];
    const float* feat = (const float*)d_in[1];
    if (n_in >= 2 && in_sizes[0] != 5 * N_ANCH) {   // defensive swap on sizes
        pred = (const float*)d_in[1];
        feat = (const float*)d_in[0];
    }
    float* out = (float*)d_out;

    fused_kernel<<<TOPK * ROI * ROI, NT>>>(pred, feat, out);
}